// round 11
// baseline (speedup 1.0000x reference)
#include <cuda_runtime.h>
#include <cuda_bf16.h>
#include <math.h>
#include <stdint.h>

// ---------------- dims ----------------
#define MD 2048
#define NQKV 6144
#define NFF 8192
#define EPS 1e-5f

// ---------------- scratch ----------------
__device__ float g_altx[32 * MD];
__device__ float g_s[32 * MD];
__device__ float g_y[32 * MD];
__device__ float g_imv[32 * MD];
__device__ float g_h[32 * NFF];
__device__ float g_part[2097152];   // 8 MB partials

// ---------------- helpers ----------------
#define SWA(o) ((o) ^ ((((o) >> 7) & 3u) << 4))

__device__ __forceinline__ uint32_t smem_u32(const void* p) {
    uint32_t a;
    asm("{ .reg .u64 t; cvta.to.shared.u64 t, %1; cvt.u32.u64 %0, t; }" : "=r"(a) : "l"(p));
    return a;
}

// cheap split: hi = truncate-to-bf16 (top 16 bits), lo = bf16(f - hi) (truncated)
__device__ __forceinline__ void pack2(float f0, float f1, uint32_t& hi, uint32_t& lo) {
    uint32_t u0 = __float_as_uint(f0), u1 = __float_as_uint(f1);
    float l0 = f0 - __uint_as_float(u0 & 0xffff0000u);
    float l1 = f1 - __uint_as_float(u1 & 0xffff0000u);
    hi = __byte_perm(u0, u1, 0x7632);
    lo = __byte_perm(__float_as_uint(l0), __float_as_uint(l1), 0x7632);
}

#define LDSM4(r0, r1, r2, r3, a) \
    asm volatile("ldmatrix.sync.aligned.m8n8.x4.shared.b16 {%0,%1,%2,%3},[%4];" \
        : "=r"(r0), "=r"(r1), "=r"(r2), "=r"(r3) : "r"(a))

#define MMA16816(d, a0, a1, a2, a3, b0, b1) \
    asm volatile("mma.sync.aligned.m16n8k16.row.col.f32.bf16.bf16.f32 " \
        "{%0,%1,%2,%3},{%4,%5,%6,%7},{%8,%9},{%0,%1,%2,%3};" \
        : "+f"((d)[0]), "+f"((d)[1]), "+f"((d)[2]), "+f"((d)[3]) \
        : "r"(a0), "r"(a1), "r"(a2), "r"(a3), "r"(b0), "r"(b1))

#define CP16(smem, gptr) \
    asm volatile("cp.async.cg.shared.global [%0], [%1], 16;" :: "r"(smem), "l"(gptr))
#define CP_COMMIT() asm volatile("cp.async.commit_group;" ::: "memory")
#define CP_WAIT1() asm volatile("cp.async.wait_group 1;" ::: "memory")

__device__ __forceinline__ float sinbias(int i, int n) {
    int j2 = n & ~1;
    float ang = (float)i * expf(-(float)j2 * (9.210340371976184f / 1024.f));
    return (n & 1) ? cosf(ang) : sinf(ang);
}

// ================ segment average ================
__global__ void avg_k(const float* __restrict__ x, float* __restrict__ altx) {
    int idx = blockIdx.x * 256 + threadIdx.x;
    int i = idx >> 11;
    int m = idx & 2047;
    int c1 = m >> 5;
    int c2 = m & 31;
    const float4* p = (const float4*)(x + ((c2 << 6) + c1) * 2048 + (i << 6));
    float s = 0.f;
#pragma unroll
    for (int t = 0; t < 16; t++) { float4 v = p[t]; s += v.x + v.y + v.z + v.w; }
    altx[idx] = s * (1.f / 64.f);
}

// ================ bf16-split GEMM: cp.async 3-stage A pipeline ================
// D[256 W-rows x 32 tokens] per CTA; warp w: rows [w*32, w*32+32).
// A stage: 256 rows x 32 floats fp32, pitch 160B. 3 stages.
// B: fp32 reg prefetch -> bf16 hi/lo smem (double buffered) -> ldmatrix.
#define APITCH 160
#define ASTG (256 * APITCH)          // 40960 B per stage
#define BOFF (3 * ASTG)              // B region after 3 A stages
#define DYNSM (BOFF + 4 * 2048)      // 131072 B

__global__ __launch_bounds__(256, 1) void gemm_mma(
    const float* __restrict__ X, const float* __restrict__ W,
    float* __restrict__ P, int N, int K, int kc)
{
    extern __shared__ __align__(16) char dynsm[];
    uint32_t sb = smem_u32(dynsm);

    int tid = threadIdx.x;
    int wid = tid >> 5, lane = tid & 31;

    int rowq = lane >> 2;
    int kpo = 2 * (lane & 3);

    // A cp.async: thread -> row tid, 8 x 16B segments per chunk
    const float* Agrow = W + ((size_t)blockIdx.x * 256 + tid) * K;
    uint32_t a_dst_row = sb + (uint32_t)(tid * APITCH);

    // B loader: thread -> token tid>>3, k-float (tid&7)*4
    int btok = tid >> 3, bkf = (tid & 7) * 4;
    const float* Bp = X + (size_t)btok * K + bkf;

    int k0 = blockIdx.y * kc;
    int NCH = kc >> 5;

    // ---- prologue: issue A chunks 0,1 ----
#pragma unroll
    for (int s = 0; s < 2; s++) {
        if (s < NCH) {
            const float* g = Agrow + k0 + s * 32;
            uint32_t dst = a_dst_row + (uint32_t)(s * ASTG);
#pragma unroll
            for (int seg = 0; seg < 8; seg++)
                CP16(dst + seg * 16, g + seg * 4);
        }
        CP_COMMIT();
    }
    float4 b4 = *(const float4*)(Bp + k0);

    float d[2][4][4];
#pragma unroll
    for (int mt = 0; mt < 2; mt++)
#pragma unroll
        for (int f = 0; f < 4; f++)
#pragma unroll
            for (int i = 0; i < 4; i++) d[mt][f][i] = 0.f;

    uint32_t boff_store = SWA((uint32_t)(btok * 64 + bkf * 2));
    uint32_t b_tokoff = (uint32_t)(((lane >> 4) * 8 + (lane & 7)) * 64);
    uint32_t b_kb = (uint32_t)(((lane >> 3) & 1) * 16);

    // per-warp A fragment base offsets (within a stage)
    uint32_t a_fr[2][2];
#pragma unroll
    for (int mt = 0; mt < 2; mt++) {
        a_fr[mt][0] = (uint32_t)((wid * 32 + mt * 16 + rowq) * APITCH + kpo * 4);
        a_fr[mt][1] = a_fr[mt][0] + 8 * APITCH;
    }

    int stg = 0;   // stage of current chunk
    for (int ch = 0; ch < NCH; ch++) {
        int bi = (ch & 1) * 2;
        // store B hi/lo into smem buffer bi
        {
            uint2 hi, lo;
            pack2(b4.x, b4.y, hi.x, lo.x);
            pack2(b4.z, b4.w, hi.y, lo.y);
            *(uint2*)(dynsm + BOFF + bi * 2048 + boff_store) = hi;
            *(uint2*)(dynsm + BOFF + (bi + 1) * 2048 + boff_store) = lo;
        }
        if (ch + 1 < NCH) b4 = *(const float4*)(Bp + k0 + (ch + 1) * 32);

        CP_WAIT1();
        __syncthreads();

        // issue A chunk ch+2 into stage (stg+2)%3
        {
            int nc = ch + 2;
            if (nc < NCH) {
                int ns = stg + 2; if (ns >= 3) ns -= 3;
                const float* g = Agrow + k0 + nc * 32;
                uint32_t dst = a_dst_row + (uint32_t)(ns * ASTG);
#pragma unroll
                for (int seg = 0; seg < 8; seg++)
                    CP16(dst + seg * 16, g + seg * 4);
            }
            CP_COMMIT();
        }

        uint32_t aS = sb + (uint32_t)(stg * ASTG);
        uint32_t bhB = sb + (uint32_t)(BOFF + bi * 2048);
        uint32_t blB = bhB + 2048;

#pragma unroll
        for (int kk = 0; kk < 2; kk++) {
            // LDS A fp32 pairs, convert to bf16 hi/lo fragments
            uint32_t ah[2][4], al[2][4];
#pragma unroll
            for (int mt = 0; mt < 2; mt++) {
                float2 f0, f1, f2, f3;
                uint32_t base0 = aS + a_fr[mt][0] + (uint32_t)(kk * 64);
                uint32_t base1 = aS + a_fr[mt][1] + (uint32_t)(kk * 64);
                asm volatile("ld.shared.v2.f32 {%0,%1},[%2];" : "=f"(f0.x), "=f"(f0.y) : "r"(base0));
                asm volatile("ld.shared.v2.f32 {%0,%1},[%2];" : "=f"(f1.x), "=f"(f1.y) : "r"(base1));
                asm volatile("ld.shared.v2.f32 {%0,%1},[%2];" : "=f"(f2.x), "=f"(f2.y) : "r"(base0 + 32));
                asm volatile("ld.shared.v2.f32 {%0,%1},[%2];" : "=f"(f3.x), "=f"(f3.y) : "r"(base1 + 32));
                pack2(f0.x, f0.y, ah[mt][0], al[mt][0]);
                pack2(f1.x, f1.y, ah[mt][1], al[mt][1]);
                pack2(f2.x, f2.y, ah[mt][2], al[mt][2]);
                pack2(f3.x, f3.y, ah[mt][3], al[mt][3]);
            }
            // B fragments
            uint32_t bh[8], bl[8];
#pragma unroll
            for (int g = 0; g < 2; g++) {
                uint32_t bo = SWA((uint32_t)(g * 16 * 64) + b_tokoff + b_kb + (uint32_t)(kk * 32));
                LDSM4(bh[g * 4 + 0], bh[g * 4 + 1], bh[g * 4 + 2], bh[g * 4 + 3], bhB + bo);
                LDSM4(bl[g * 4 + 0], bl[g * 4 + 1], bl[g * 4 + 2], bl[g * 4 + 3], blB + bo);
            }
            // 24 MMAs
#pragma unroll
            for (int mt = 0; mt < 2; mt++)
#pragma unroll
                for (int f = 0; f < 4; f++)
                    MMA16816(d[mt][f], ah[mt][0], ah[mt][1], ah[mt][2], ah[mt][3],
                             bh[f * 2], bh[f * 2 + 1]);
#pragma unroll
            for (int mt = 0; mt < 2; mt++)
#pragma unroll
                for (int f = 0; f < 4; f++)
                    MMA16816(d[mt][f], ah[mt][0], ah[mt][1], ah[mt][2], ah[mt][3],
                             bl[f * 2], bl[f * 2 + 1]);
#pragma unroll
            for (int mt = 0; mt < 2; mt++)
#pragma unroll
                for (int f = 0; f < 4; f++)
                    MMA16816(d[mt][f], al[mt][0], al[mt][1], al[mt][2], al[mt][3],
                             bh[f * 2], bh[f * 2 + 1]);
        }
        if (++stg == 3) stg = 0;
    }
    __syncthreads();

    // ---- epilogue: transpose via smem (pitch 260 floats) ----
    float* ep = (float*)dynsm;
#pragma unroll
    for (int mt = 0; mt < 2; mt++)
#pragma unroll
        for (int f = 0; f < 4; f++)
#pragma unroll
            for (int i = 0; i < 4; i++) {
                int m = wid * 32 + mt * 16 + (lane >> 2) + ((i >> 1) << 3);
                int tok = f * 8 + (lane & 3) * 2 + (i & 1);
                ep[tok * 260 + m] = d[mt][f][i];
            }
    __syncthreads();
    {
        size_t pb = (size_t)blockIdx.y * 32 * N + (size_t)blockIdx.x * 256;
        for (int e = tid; e < 8192; e += 256) {
            int tok = e >> 8, col = e & 255;
            P[pb + (size_t)tok * N + col] = ep[tok * 260 + col];
        }
    }
}

// ================ LN stat helper ================
__device__ __forceinline__ void ln_stats(float sum, float sq, float* red, int tid,
                                         float& mu, float& rstd) {
    int w = tid >> 5, lane = tid & 31;
#pragma unroll
    for (int off = 16; off; off >>= 1) {
        sum += __shfl_xor_sync(0xffffffffu, sum, off);
        sq  += __shfl_xor_sync(0xffffffffu, sq, off);
    }
    if (lane == 0) { red[w] = sum; red[32 + w] = sq; }
    __syncthreads();
    if (tid == 0) {
        float a = 0.f, b = 0.f;
        for (int k = 0; k < 8; k++) { a += red[k]; b += red[32 + k]; }
        red[60] = a; red[61] = b;
    }
    __syncthreads();
    mu = red[60] * (1.f / 2048.f);
    float var = red[61] * (1.f / 2048.f) - mu * mu;
    rstd = rsqrtf(var + EPS);
}

// ================ fused epilogues ================
__global__ void postA_k(const float* __restrict__ P, float* __restrict__ s,
                        float* __restrict__ y, const float* __restrict__ g,
                        const float* __restrict__ bt, int ks)
{
    __shared__ float red[64];
    int i = blockIdx.x, tid = threadIdx.x;
    float v[8]; float sum = 0.f, sq = 0.f;
#pragma unroll
    for (int j = 0; j < 8; j++) {
        int n = tid + j * 256;
        float a = 0.f;
        for (int sp = 0; sp < ks; sp++) a += P[(size_t)sp * 65536 + i * 2048 + n];
        a += sinbias(i, n);
        v[j] = a; s[i * 2048 + n] = a; sum += a; sq += a * a;
    }
    float mu, rstd;
    ln_stats(sum, sq, red, tid, mu, rstd);
#pragma unroll
    for (int j = 0; j < 8; j++) {
        int n = tid + j * 256;
        y[i * 2048 + n] = (v[j] - mu) * rstd * g[n] + bt[n];
    }
}

__global__ void postB_k(const float* __restrict__ P, float* __restrict__ s,
                        const float* __restrict__ g, const float* __restrict__ bt, int ks)
{
    __shared__ float red[64];
    int i = blockIdx.x, tid = threadIdx.x;
    float v[8]; float sum = 0.f, sq = 0.f;
#pragma unroll
    for (int j = 0; j < 8; j++) {
        int n = tid + j * 256;
        float a = 0.f;
        for (int sp = 0; sp < ks; sp++) a += P[(size_t)sp * 65536 + i * 2048 + n];
        a += s[i * 2048 + n];
        v[j] = a; sum += a; sq += a * a;
    }
    float mu, rstd;
    ln_stats(sum, sq, red, tid, mu, rstd);
#pragma unroll
    for (int j = 0; j < 8; j++) {
        int n = tid + j * 256;
        s[i * 2048 + n] = (v[j] - mu) * rstd * g[n] + bt[n] + v[j];
    }
}

__global__ void postC_k(const float* __restrict__ P, float* __restrict__ h,
                        const float* __restrict__ bias, int ks)
{
    int base = blockIdx.x * 1024 + threadIdx.x;
#pragma unroll
    for (int j = 0; j < 4; j++) {
        int e = base + j * 256;
        int i = e >> 13, n = e & 8191;
        float a = 0.f;
        for (int sp = 0; sp < ks; sp++) a += P[(size_t)sp * 262144 + i * 8192 + n];
        a += bias[n];
        h[e] = 0.5f * a * (1.f + erff(a * 0.70710678118654752f));
    }
}

__global__ void postD_k(const float* __restrict__ P, float* __restrict__ s,
                        float* __restrict__ y, const float* __restrict__ bias,
                        const float* __restrict__ g, const float* __restrict__ bt,
                        float* __restrict__ out, int last, int ks)
{
    __shared__ float red[64];
    int i = blockIdx.x, tid = threadIdx.x;
    float v[8]; float sum = 0.f, sq = 0.f;
#pragma unroll
    for (int j = 0; j < 8; j++) {
        int n = tid + j * 256;
        float a = 0.f;
        for (int sp = 0; sp < ks; sp++) a += P[(size_t)sp * 65536 + i * 2048 + n];
        a += bias[n];
        v[j] = a; sum += a; sq += a * a;
    }
    if (last) {
#pragma unroll
        for (int j = 0; j < 8; j++) out[i * 2048 + tid + j * 256] = v[j];
        return;
    }
    float mu, rstd;
    ln_stats(sum, sq, red, tid, mu, rstd);
#pragma unroll
    for (int j = 0; j < 8; j++) {
        int n = tid + j * 256;
        s[i * 2048 + n] = v[j];
        y[i * 2048 + n] = (v[j] - mu) * rstd * g[n] + bt[n];
    }
}

// ================ scalar attention + cumsum (fused qkv split-K sum) ================
__global__ void attn_k(const float* __restrict__ P, float* __restrict__ imv, int ks) {
    const size_t ST = (size_t)32 * 6144;
    int h = blockIdx.x;
    int tid = threadIdx.x;
    int w = tid >> 5, lane = tid & 31;
    __shared__ float rsa[32];

#pragma unroll
    for (int ii = 0; ii < 8; ii++) {
        int i = w * 8 + ii;
        size_t qb = (size_t)i * 6144 + h * 128 + lane * 4;
        float4 qa = make_float4(0.f, 0.f, 0.f, 0.f), ka = make_float4(0.f, 0.f, 0.f, 0.f);
        for (int sp = 0; sp < ks; sp++) {
            float4 q = *(const float4*)&P[sp * ST + qb];
            float4 k = *(const float4*)&P[sp * ST + qb + 2048];
            qa.x += q.x; qa.y += q.y; qa.z += q.z; qa.w += q.w;
            ka.x += k.x; ka.y += k.y; ka.z += k.z; ka.w += k.w;
        }
        float p = qa.x * ka.x + qa.y * ka.y + qa.z * ka.z + qa.w * ka.w;
#pragma unroll
        for (int off = 16; off; off >>= 1) p += __shfl_xor_sync(0xffffffffu, p, off);
        if (lane == 0) rsa[i] = p * 0.08838834764831845f;
    }
    __syncthreads();

    int d = tid;
    float run = 0.f;
#pragma unroll
    for (int i = 0; i < 32; i++) {
        size_t vb = (size_t)i * 6144 + 4096 + h * 128 + d;
        float vv = 0.f;
        for (int sp = 0; sp < ks; sp++) vv += P[sp * ST + vb];
        run += rsa[i] * vv;
        imv[i * 2048 + h * 128 + d] = run;
    }
}

// ================ launch ================
extern "C" void kernel_launch(void* const* d_in, const int* in_sizes, int n_in,
                              void* d_out, int out_size)
{
    const float* x      = (const float*)d_in[0];
    const float* weight = (const float*)d_in[1];
    const float* Wqkv   = (const float*)d_in[2];
    const float* Wo     = (const float*)d_in[3];
    const float* ln1_g  = (const float*)d_in[4];
    const float* ln1_b  = (const float*)d_in[5];
    const float* ln2_g  = (const float*)d_in[6];
    const float* ln2_b  = (const float*)d_in[7];
    const float* fc1_w  = (const float*)d_in[8];
    const float* fc1_b  = (const float*)d_in[9];
    const float* fc2_w  = (const float*)d_in[10];
    const float* fc2_b  = (const float*)d_in[11];
    float* out = (float*)d_out;

    float *p_altx, *p_s, *p_y, *p_imv, *p_h, *p_part;
    cudaGetSymbolAddress((void**)&p_altx, g_altx);
    cudaGetSymbolAddress((void**)&p_s,    g_s);
    cudaGetSymbolAddress((void**)&p_y,    g_y);
    cudaGetSymbolAddress((void**)&p_imv,  g_imv);
    cudaGetSymbolAddress((void**)&p_h,    g_h);
    cudaGetSymbolAddress((void**)&p_part, g_part);

    cudaFuncSetAttribute(gemm_mma, cudaFuncAttributeMaxDynamicSharedMemorySize, DYNSM);

    avg_k<<<256, 256>>>(x, p_altx);

    // s = weight @ altx^T + sinbias ; y = LN1(s)   (N=2048, ks=16, kc=128)
    gemm_mma<<<dim3(8, 16), 256, DYNSM>>>(p_altx, weight, p_part, MD, MD, 128);
    postA_k<<<32, 256>>>(p_part, p_s, p_y, ln1_g, ln1_b, 16);

    for (int a = 0; a < 3; a++) {
        // qkv   (N=6144, ks=8, kc=256)
        gemm_mma<<<dim3(24, 8), 256, DYNSM>>>(p_y, Wqkv + (size_t)a * NQKV * MD,
                                              p_part, NQKV, MD, 256);
        attn_k<<<16, 128>>>(p_part, p_imv, 8);

        // Wo    (N=2048, ks=16, kc=128)
        gemm_mma<<<dim3(8, 16), 256, DYNSM>>>(p_imv, Wo + (size_t)a * MD * MD,
                                              p_part, MD, MD, 128);
        postB_k<<<32, 256>>>(p_part, p_s, ln2_g, ln2_b, 16);

        // fc1   (N=8192, ks=8, kc=256)
        gemm_mma<<<dim3(32, 8), 256, DYNSM>>>(p_s, fc1_w, p_part, NFF, MD, 256);
        postC_k<<<256, 256>>>(p_part, p_h, fc1_b, 8);

        // fc2   (N=2048, K=8192, ks=32, kc=256)
        gemm_mma<<<dim3(8, 32), 256, DYNSM>>>(p_h, fc2_w, p_part, MD, NFF, 256);
        postD_k<<<32, 256>>>(p_part, p_s, p_y, fc2_b, ln1_g, ln1_b, out, a == 2, 32);
    }
}

// round 12
// speedup vs baseline: 1.2869x; 1.2869x over previous
#include <cuda_runtime.h>
#include <cuda_bf16.h>
#include <math.h>
#include <stdint.h>

// ---------------- dims ----------------
#define MD 2048
#define NQKV 6144
#define NFF 8192
#define EPS 1e-5f

// ---------------- scratch ----------------
__device__ float g_altx[32 * MD];
__device__ float g_s[32 * MD];
__device__ float g_y[32 * MD];
__device__ float g_imv[32 * MD];
__device__ float g_part[2097152];    // 8 MB partials (qkv/wo/fc2/embed)
__device__ float g_part2[2097152];   // 8 MB partials (fc1 -> consumed by fc2)

// ---------------- helpers ----------------
#define SWA(o) ((o) ^ ((((o) >> 7) & 3u) << 4))

__device__ __forceinline__ uint32_t smem_u32(const void* p) {
    uint32_t a;
    asm("{ .reg .u64 t; cvta.to.shared.u64 t, %1; cvt.u32.u64 %0, t; }" : "=r"(a) : "l"(p));
    return a;
}

// cheap split: hi = truncate-to-bf16 (top 16 bits), lo = bf16(f - hi) (truncated)
__device__ __forceinline__ void pack2(float f0, float f1, uint32_t& hi, uint32_t& lo) {
    uint32_t u0 = __float_as_uint(f0), u1 = __float_as_uint(f1);
    float l0 = f0 - __uint_as_float(u0 & 0xffff0000u);
    float l1 = f1 - __uint_as_float(u1 & 0xffff0000u);
    hi = __byte_perm(u0, u1, 0x7632);
    lo = __byte_perm(__float_as_uint(l0), __float_as_uint(l1), 0x7632);
}

#define LDSM4(r0, r1, r2, r3, a) \
    asm volatile("ldmatrix.sync.aligned.m8n8.x4.shared.b16 {%0,%1,%2,%3},[%4];" \
        : "=r"(r0), "=r"(r1), "=r"(r2), "=r"(r3) : "r"(a))

#define MMA16816(d, a0, a1, a2, a3, b0, b1) \
    asm volatile("mma.sync.aligned.m16n8k16.row.col.f32.bf16.bf16.f32 " \
        "{%0,%1,%2,%3},{%4,%5,%6,%7},{%8,%9},{%0,%1,%2,%3};" \
        : "+f"((d)[0]), "+f"((d)[1]), "+f"((d)[2]), "+f"((d)[3]) \
        : "r"(a0), "r"(a1), "r"(a2), "r"(a3), "r"(b0), "r"(b1))

__device__ __forceinline__ float sinbias(int i, int n) {
    int j2 = n & ~1;
    float ang = (float)i * expf(-(float)j2 * (9.210340371976184f / 1024.f));
    return (n & 1) ? cosf(ang) : sinf(ang);
}

__device__ __forceinline__ float gelu_f(float a) {
    return 0.5f * a * (1.f + erff(a * 0.70710678118654752f));
}

// ================ segment average ================
__global__ void avg_k(const float* __restrict__ x, float* __restrict__ altx) {
    int idx = blockIdx.x * 256 + threadIdx.x;
    int i = idx >> 11;
    int m = idx & 2047;
    int c1 = m >> 5;
    int c2 = m & 31;
    const float4* p = (const float4*)(x + ((c2 << 6) + c1) * 2048 + (i << 6));
    float s = 0.f;
#pragma unroll
    for (int t = 0; t < 16; t++) { float4 v = p[t]; s += v.x + v.y + v.z + v.w; }
    altx[idx] = s * (1.f / 64.f);
}

// ================ bf16-split GEMM, sync-free mainloop ================
// D[256 W-rows x 32 tokens] per CTA; warp w: rows [w*32, w*32+32).
// B k-slice (32 tokens x kc) preloaded ONCE to smem as bf16 hi/lo, then the
// whole K loop runs with zero __syncthreads (warps self-paced).
// mode 0: B = X[tok][k] fp32.   mode 1 (fc2): B = gelu(sum_{sp<8} X[sp*32K + tok*K + k] + bias[k]).
// Partials out: P[split][token][row_global].
#define MAXNCH 8

__global__ __launch_bounds__(256, 2) void gemm_mma(
    const float* __restrict__ X, const float* __restrict__ W,
    float* __restrict__ P, int N, int K, int kc, int mode,
    const float* __restrict__ bias)
{
    __shared__ __align__(16) union SU {
        char b[MAXNCH * 4096];    // per chunk: [hi 2048][lo 2048]
        float ep[32 * 260];
    } sm;

    int tid = threadIdx.x;
    int wid = tid >> 5, lane = tid & 31;

    int rowq = lane >> 2;
    int kpo = 2 * (lane & 3);
    const float* A0 = W + ((size_t)blockIdx.x * 256 + wid * 32 + rowq) * K + kpo;
    size_t rK8 = (size_t)8 * K;

    int k0 = blockIdx.y * kc;
    int NCH = kc >> 5;
    int NST = NCH * 2;

    // ---- A prologue: fragment regs for step 0 (issued before B phase) ----
    float2 af[8];
    {
        const float* Ab = A0 + k0;
#pragma unroll
        for (int mt = 0; mt < 2; mt++) {
            const float* Am = Ab + (size_t)mt * 16 * K;
            af[mt * 4 + 0] = *(const float2*)(Am);
            af[mt * 4 + 1] = *(const float2*)(Am + rK8);
            af[mt * 4 + 2] = *(const float2*)(Am + 8);
            af[mt * 4 + 3] = *(const float2*)(Am + rK8 + 8);
        }
    }

    // ---- B phase: load/convert entire k-slice into smem ----
    {
        int btok = tid >> 3, bkf = (tid & 7) * 4;
        uint32_t blocal = SWA((uint32_t)(btok * 64 + bkf * 2));
        for (int c = 0; c < NCH; c++) {
            int kg = k0 + c * 32 + bkf;
            float4 b4;
            if (mode == 0) {
                b4 = *(const float4*)&X[(size_t)btok * K + kg];
            } else {
                const float* pp = X + (size_t)btok * K + kg;
                size_t sps = (size_t)32 * K;
                b4 = make_float4(0.f, 0.f, 0.f, 0.f);
#pragma unroll
                for (int sp = 0; sp < 8; sp++) {
                    float4 q = *(const float4*)&pp[sp * sps];
                    b4.x += q.x; b4.y += q.y; b4.z += q.z; b4.w += q.w;
                }
                float4 bb = *(const float4*)&bias[kg];
                b4.x = gelu_f(b4.x + bb.x);
                b4.y = gelu_f(b4.y + bb.y);
                b4.z = gelu_f(b4.z + bb.z);
                b4.w = gelu_f(b4.w + bb.w);
            }
            uint2 hi, lo;
            pack2(b4.x, b4.y, hi.x, lo.x);
            pack2(b4.z, b4.w, hi.y, lo.y);
            *(uint2*)(sm.b + c * 4096 + blocal) = hi;
            *(uint2*)(sm.b + c * 4096 + 2048 + blocal) = lo;
        }
    }
    __syncthreads();   // the only sync before the epilogue

    float d[2][4][4];
#pragma unroll
    for (int mt = 0; mt < 2; mt++)
#pragma unroll
        for (int f = 0; f < 4; f++)
#pragma unroll
            for (int i = 0; i < 4; i++) d[mt][f][i] = 0.f;

    uint32_t sb = smem_u32(&sm);
    uint32_t b_tokoff = (uint32_t)(((lane >> 4) * 8 + (lane & 7)) * 64);
    uint32_t b_kb = (uint32_t)(((lane >> 3) & 1) * 16);

    // ---- sync-free mainloop ----
    for (int ch = 0; ch < NCH; ch++) {
        uint32_t bhB = sb + (uint32_t)(ch * 4096);
        uint32_t blB = bhB + 2048;
#pragma unroll
        for (int kk = 0; kk < 2; kk++) {
            int st = ch * 2 + kk;
            uint32_t ah[2][4], al[2][4];
#pragma unroll
            for (int mt = 0; mt < 2; mt++)
#pragma unroll
                for (int j = 0; j < 4; j++)
                    pack2(af[mt * 4 + j].x, af[mt * 4 + j].y, ah[mt][j], al[mt][j]);
            if (st + 1 < NST) {
                const float* An = A0 + k0 + (st + 1) * 16;
#pragma unroll
                for (int mt = 0; mt < 2; mt++) {
                    const float* Am = An + (size_t)mt * 16 * K;
                    af[mt * 4 + 0] = *(const float2*)(Am);
                    af[mt * 4 + 1] = *(const float2*)(Am + rK8);
                    af[mt * 4 + 2] = *(const float2*)(Am + 8);
                    af[mt * 4 + 3] = *(const float2*)(Am + rK8 + 8);
                }
            }
            uint32_t bh[8], bl[8];
#pragma unroll
            for (int g = 0; g < 2; g++) {
                uint32_t bo = SWA((uint32_t)(g * 16 * 64) + b_tokoff + b_kb + (uint32_t)(kk * 32));
                LDSM4(bh[g * 4 + 0], bh[g * 4 + 1], bh[g * 4 + 2], bh[g * 4 + 3], bhB + bo);
                LDSM4(bl[g * 4 + 0], bl[g * 4 + 1], bl[g * 4 + 2], bl[g * 4 + 3], blB + bo);
            }
#pragma unroll
            for (int mt = 0; mt < 2; mt++)
#pragma unroll
                for (int f = 0; f < 4; f++)
                    MMA16816(d[mt][f], ah[mt][0], ah[mt][1], ah[mt][2], ah[mt][3],
                             bh[f * 2], bh[f * 2 + 1]);
#pragma unroll
            for (int mt = 0; mt < 2; mt++)
#pragma unroll
                for (int f = 0; f < 4; f++)
                    MMA16816(d[mt][f], ah[mt][0], ah[mt][1], ah[mt][2], ah[mt][3],
                             bl[f * 2], bl[f * 2 + 1]);
#pragma unroll
            for (int mt = 0; mt < 2; mt++)
#pragma unroll
                for (int f = 0; f < 4; f++)
                    MMA16816(d[mt][f], al[mt][0], al[mt][1], al[mt][2], al[mt][3],
                             bh[f * 2], bh[f * 2 + 1]);
        }
    }
    __syncthreads();

    // ---- epilogue: transpose via smem (pitch 260 floats) ----
#pragma unroll
    for (int mt = 0; mt < 2; mt++)
#pragma unroll
        for (int f = 0; f < 4; f++)
#pragma unroll
            for (int i = 0; i < 4; i++) {
                int m = wid * 32 + mt * 16 + (lane >> 2) + ((i >> 1) << 3);
                int tok = f * 8 + (lane & 3) * 2 + (i & 1);
                sm.ep[tok * 260 + m] = d[mt][f][i];
            }
    __syncthreads();
    {
        size_t pb = (size_t)blockIdx.y * 32 * N + (size_t)blockIdx.x * 256;
        for (int e = tid; e < 8192; e += 256) {
            int tok = e >> 8, col = e & 255;
            P[pb + (size_t)tok * N + col] = sm.ep[tok * 260 + col];
        }
    }
}

// ================ LN stat helper ================
__device__ __forceinline__ void ln_stats(float sum, float sq, float* red, int tid,
                                         float& mu, float& rstd) {
    int w = tid >> 5, lane = tid & 31;
#pragma unroll
    for (int off = 16; off; off >>= 1) {
        sum += __shfl_xor_sync(0xffffffffu, sum, off);
        sq  += __shfl_xor_sync(0xffffffffu, sq, off);
    }
    if (lane == 0) { red[w] = sum; red[32 + w] = sq; }
    __syncthreads();
    if (tid == 0) {
        float a = 0.f, b = 0.f;
        for (int k = 0; k < 8; k++) { a += red[k]; b += red[32 + k]; }
        red[60] = a; red[61] = b;
    }
    __syncthreads();
    mu = red[60] * (1.f / 2048.f);
    float var = red[61] * (1.f / 2048.f) - mu * mu;
    rstd = rsqrtf(var + EPS);
}

// ================ fused epilogues ================
__global__ void postA_k(const float* __restrict__ P, float* __restrict__ s,
                        float* __restrict__ y, const float* __restrict__ g,
                        const float* __restrict__ bt, int ks)
{
    __shared__ float red[64];
    int i = blockIdx.x, tid = threadIdx.x;
    float v[8]; float sum = 0.f, sq = 0.f;
#pragma unroll
    for (int j = 0; j < 8; j++) {
        int n = tid + j * 256;
        float a = 0.f;
        for (int sp = 0; sp < ks; sp++) a += P[(size_t)sp * 65536 + i * 2048 + n];
        a += sinbias(i, n);
        v[j] = a; s[i * 2048 + n] = a; sum += a; sq += a * a;
    }
    float mu, rstd;
    ln_stats(sum, sq, red, tid, mu, rstd);
#pragma unroll
    for (int j = 0; j < 8; j++) {
        int n = tid + j * 256;
        y[i * 2048 + n] = (v[j] - mu) * rstd * g[n] + bt[n];
    }
}

__global__ void postB_k(const float* __restrict__ P, float* __restrict__ s,
                        const float* __restrict__ g, const float* __restrict__ bt, int ks)
{
    __shared__ float red[64];
    int i = blockIdx.x, tid = threadIdx.x;
    float v[8]; float sum = 0.f, sq = 0.f;
#pragma unroll
    for (int j = 0; j < 8; j++) {
        int n = tid + j * 256;
        float a = 0.f;
        for (int sp = 0; sp < ks; sp++) a += P[(size_t)sp * 65536 + i * 2048 + n];
        a += s[i * 2048 + n];
        v[j] = a; sum += a; sq += a * a;
    }
    float mu, rstd;
    ln_stats(sum, sq, red, tid, mu, rstd);
#pragma unroll
    for (int j = 0; j < 8; j++) {
        int n = tid + j * 256;
        s[i * 2048 + n] = (v[j] - mu) * rstd * g[n] + bt[n] + v[j];
    }
}

__global__ void postD_k(const float* __restrict__ P, float* __restrict__ s,
                        float* __restrict__ y, const float* __restrict__ bias,
                        const float* __restrict__ g, const float* __restrict__ bt,
                        float* __restrict__ out, int last, int ks)
{
    __shared__ float red[64];
    int i = blockIdx.x, tid = threadIdx.x;
    float v[8]; float sum = 0.f, sq = 0.f;
#pragma unroll
    for (int j = 0; j < 8; j++) {
        int n = tid + j * 256;
        float a = 0.f;
        for (int sp = 0; sp < ks; sp++) a += P[(size_t)sp * 65536 + i * 2048 + n];
        a += bias[n];
        v[j] = a; sum += a; sq += a * a;
    }
    if (last) {
#pragma unroll
        for (int j = 0; j < 8; j++) out[i * 2048 + tid + j * 256] = v[j];
        return;
    }
    float mu, rstd;
    ln_stats(sum, sq, red, tid, mu, rstd);
#pragma unroll
    for (int j = 0; j < 8; j++) {
        int n = tid + j * 256;
        s[i * 2048 + n] = v[j];
        y[i * 2048 + n] = (v[j] - mu) * rstd * g[n] + bt[n];
    }
}

// ================ scalar attention + cumsum (fused qkv split-K sum) ================
__global__ void attn_k(const float* __restrict__ P, float* __restrict__ imv, int ks) {
    const size_t ST = (size_t)32 * 6144;
    int h = blockIdx.x;
    int tid = threadIdx.x;
    int w = tid >> 5, lane = tid & 31;
    __shared__ float rsa[32];

#pragma unroll
    for (int ii = 0; ii < 8; ii++) {
        int i = w * 8 + ii;
        size_t qb = (size_t)i * 6144 + h * 128 + lane * 4;
        float4 qa = make_float4(0.f, 0.f, 0.f, 0.f), ka = make_float4(0.f, 0.f, 0.f, 0.f);
        for (int sp = 0; sp < ks; sp++) {
            float4 q = *(const float4*)&P[sp * ST + qb];
            float4 k = *(const float4*)&P[sp * ST + qb + 2048];
            qa.x += q.x; qa.y += q.y; qa.z += q.z; qa.w += q.w;
            ka.x += k.x; ka.y += k.y; ka.z += k.z; ka.w += k.w;
        }
        float p = qa.x * ka.x + qa.y * ka.y + qa.z * ka.z + qa.w * ka.w;
#pragma unroll
        for (int off = 16; off; off >>= 1) p += __shfl_xor_sync(0xffffffffu, p, off);
        if (lane == 0) rsa[i] = p * 0.08838834764831845f;
    }
    __syncthreads();

    int d = tid;
    float run = 0.f;
#pragma unroll
    for (int i = 0; i < 32; i++) {
        size_t vb = (size_t)i * 6144 + 4096 + h * 128 + d;
        float vv = 0.f;
        for (int sp = 0; sp < ks; sp++) vv += P[sp * ST + vb];
        run += rsa[i] * vv;
        imv[i * 2048 + h * 128 + d] = run;
    }
}

// ================ launch ================
extern "C" void kernel_launch(void* const* d_in, const int* in_sizes, int n_in,
                              void* d_out, int out_size)
{
    const float* x      = (const float*)d_in[0];
    const float* weight = (const float*)d_in[1];
    const float* Wqkv   = (const float*)d_in[2];
    const float* Wo     = (const float*)d_in[3];
    const float* ln1_g  = (const float*)d_in[4];
    const float* ln1_b  = (const float*)d_in[5];
    const float* ln2_g  = (const float*)d_in[6];
    const float* ln2_b  = (const float*)d_in[7];
    const float* fc1_w  = (const float*)d_in[8];
    const float* fc1_b  = (const float*)d_in[9];
    const float* fc2_w  = (const float*)d_in[10];
    const float* fc2_b  = (const float*)d_in[11];
    float* out = (float*)d_out;

    float *p_altx, *p_s, *p_y, *p_imv, *p_part, *p_part2;
    cudaGetSymbolAddress((void**)&p_altx, g_altx);
    cudaGetSymbolAddress((void**)&p_s,    g_s);
    cudaGetSymbolAddress((void**)&p_y,    g_y);
    cudaGetSymbolAddress((void**)&p_imv,  g_imv);
    cudaGetSymbolAddress((void**)&p_part, g_part);
    cudaGetSymbolAddress((void**)&p_part2, g_part2);

    avg_k<<<256, 256>>>(x, p_altx);

    // s = weight @ altx^T + sinbias ; y = LN1(s)   (N=2048, ks=16, kc=128)
    gemm_mma<<<dim3(8, 16), 256>>>(p_altx, weight, p_part, MD, MD, 128, 0, nullptr);
    postA_k<<<32, 256>>>(p_part, p_s, p_y, ln1_g, ln1_b, 16);

    for (int a = 0; a < 3; a++) {
        // qkv   (N=6144, ks=8, kc=256)
        gemm_mma<<<dim3(24, 8), 256>>>(p_y, Wqkv + (size_t)a * NQKV * MD,
                                       p_part, NQKV, MD, 256, 0, nullptr);
        attn_k<<<16, 128>>>(p_part, p_imv, 8);

        // Wo    (N=2048, ks=16, kc=128)
        gemm_mma<<<dim3(8, 16), 256>>>(p_imv, Wo + (size_t)a * MD * MD,
                                       p_part, MD, MD, 128, 0, nullptr);
        postB_k<<<32, 256>>>(p_part, p_s, ln2_g, ln2_b, 16);

        // fc1   (N=8192, ks=8, kc=256) -> part2
        gemm_mma<<<dim3(32, 8), 256>>>(p_s, fc1_w, p_part2, NFF, MD, 256, 0, nullptr);

        // fc2   (N=2048, K=8192, ks=32, kc=256); B = gelu(reduce(part2)+fc1_b) fused
        gemm_mma<<<dim3(8, 32), 256>>>(p_part2, fc2_w, p_part, MD, NFF, 256, 1, fc1_b);
        postD_k<<<32, 256>>>(p_part, p_s, p_y, fc2_b, ln1_g, ln1_b, out, a == 2, 32);
    }
}